// round 16
// baseline (speedup 1.0000x reference)
#include <cuda_runtime.h>
#include <math.h>

#define BB 32
#define TT 50
#define SS 2048
#define CC 8
#define FF 32
#define SH 1024
#define NG 128          // 4*F gates
#define RDIM 80         // 16 (x patch) + 64 (h patch)
#define NWARPS 24
#define NP 11           // slots per warp (24*11 = 264)
#define SLOTS (NWARPS*NP)   // 264 slots per CTA (ranks 0-2 own 264, rank 3 owns 232)
#define NTHREADS 768
#define HROWS 265       // 264 slot rows + 1 halo row (per parity buffer)
#define HBUF (HROWS*FF) // ull entries per parity buffer
#define XS_N (SLOTS*16) // 4224 x entries per step
#define CLUSTER_X 4
#define XTOT (BB*TT*SS*CC)

typedef unsigned long long ull;

__device__ __forceinline__ float hsig(float x) {
    return __saturatef(fmaf(x, 0.2f, 0.5f));
}

// fast tanh: 1 - 2/(exp(2x)+1); abs err ~1e-6, exact saturation
__device__ __forceinline__ float ftanh(float x) {
    float e = __expf(2.0f * x);
    return 1.0f - __fdividef(2.0f, e + 1.0f);
}

__device__ __forceinline__ ull fma2(ull a, ull b, ull c) {
    ull d;
    asm("fma.rn.f32x2 %0, %1, %2, %3;" : "=l"(d) : "l"(a), "l"(b), "l"(c));
    return d;
}
__device__ __forceinline__ ull dup2(float v) {
    ull d;
    asm("mov.b64 %0, {%1, %1};" : "=l"(d) : "f"(v));
    return d;
}
__device__ __forceinline__ ull pack2(float lo, float hi) {
    ull d;
    asm("mov.b64 %0, {%1, %2};" : "=l"(d) : "f"(lo), "f"(hi));
    return d;
}
__device__ __forceinline__ float2 unpack2(ull d) {
    float lo, hi;
    asm("mov.b64 {%0, %1}, %2;" : "=f"(lo), "=f"(hi) : "l"(d));
    return make_float2(lo, hi);
}
__device__ __forceinline__ unsigned smem_u32(const void* p) {
    unsigned a;
    asm("{ .reg .u64 t; cvta.to.shared.u64 t, %1; cvt.u32.u64 %0, t; }"
        : "=r"(a) : "l"(p));
    return a;
}

// out[b] = db[0] before lstm_kernel atomically accumulates the dense dot.
__global__ void init_out_kernel(const float* __restrict__ db, float* __restrict__ out) {
    if (threadIdx.x < BB) out[threadIdx.x] = db[0];
}

// All 50 timesteps + fused Dense(1) in ONE launch.
// Grid (4, 32) = 128 CTAs; cluster (4,1,1) = one batch per cluster.
// smem: w4s 40960B | xsD 33792B | hsD 2*265*32*8 = 135680B -> 210432B
__global__ __launch_bounds__(NTHREADS, 1) __cluster_dims__(CLUSTER_X, 1, 1)
void lstm_kernel(const float* __restrict__ x, const float* __restrict__ kern,
                 const float* __restrict__ rk, const float* __restrict__ bias,
                 const float* __restrict__ dw, float* __restrict__ out) {
    extern __shared__ float smem[];
    float4* w4s = (float4*)smem;                 // 2560 float4
    ull* xsD = (ull*)(smem + RDIM * FF * 4);     // XS_N duplicated pairs
    ull* hsD = xsD + XS_N;                       // 2 parity buffers of HBUF

    const int b = blockIdx.y;
    const int rank = blockIdx.x;                 // cluster cta rank (grid.x == 4)
    const int p0 = rank * SLOTS;                 // ranks 0-2: 264 each; rank 3: 232 live
    const int tid = threadIdx.x;
    const int f = tid & 31;
    const int w = tid >> 5;
    const int pl = w * NP;

    // ---- build weights in smem (once for all 50 steps)
    for (int i = tid; i < RDIM * FF; i += NTHREADS) {
        int r = i >> 5, ff = i & 31;
        const float* src;
        if (r < 16) {
            src = kern + ((r >> 3) * CC + (r & 7)) * NG;
        } else {
            int rr = r - 16;
            src = rk + ((rr >> 5) * FF + (rr & 31)) * NG;
        }
        w4s[i] = make_float4(src[ff], src[32 + ff], src[64 + ff], src[96 + ff]);
    }
    // ---- h state = 0 (both parity buffers incl. halo rows)
    for (int i = tid; i < 2 * HBUF; i += NTHREADS) hsD[i] = 0ULL;
    // ---- x tile for t = 0 (pre-duplicated pairs, warp-private region; guarded)
    {
        const int base4 = (((b * TT) * SS + 2 * p0) * CC) >> 2;
        const float4* xsrc = (const float4*)x;
        for (int q = f; q < NP * 4; q += 32) {
            int li = pl * 4 + q;
            int gi = base4 + li;
            float4 v = (gi < XTOT / 4) ? xsrc[gi] : make_float4(0.f, 0.f, 0.f, 0.f);
            xsD[li * 4 + 0] = dup2(v.x);
            xsD[li * 4 + 1] = dup2(v.y);
            xsD[li * 4 + 2] = dup2(v.z);
            xsD[li * 4 + 3] = dup2(v.w);
        }
    }
    // ---- c state in registers for the whole sequence
    float creg[NP];
    #pragma unroll
    for (int j = 0; j < NP; j++) creg[j] = 0.0f;

    const ull b01 = pack2(bias[f], bias[32 + f]);
    const ull b23 = pack2(bias[64 + f], bias[96 + f]);

    // init (incl. remote-targeted halo rows) must be cluster-visible
    asm volatile("barrier.cluster.arrive.aligned;" ::: "memory");
    asm volatile("barrier.cluster.wait.aligned;" ::: "memory");

    for (int t = 0; t < TT; t++) {
        const int par = t & 1;
        ull* hrd = hsD + par * HBUF;          // read current h
        ull* hwr = hsD + (par ^ 1) * HBUF;    // write next h

        ull acc[NP][2];
        #pragma unroll
        for (int j = 0; j < NP; j++) { acc[j][0] = b01; acc[j][1] = b23; }

        // ---- x-patch (r = 0..15): 4-row weight groups, pre-duplicated pairs
        #pragma unroll
        for (int rg = 0; rg < 4; rg++) {
            ulonglong2 wv0 = *(const ulonglong2*)&w4s[(rg * 4 + 0) * FF + f];
            ulonglong2 wv1 = *(const ulonglong2*)&w4s[(rg * 4 + 1) * FF + f];
            ulonglong2 wv2 = *(const ulonglong2*)&w4s[(rg * 4 + 2) * FF + f];
            ulonglong2 wv3 = *(const ulonglong2*)&w4s[(rg * 4 + 3) * FF + f];
            #pragma unroll
            for (int j = 0; j < NP; j++) {
                ulonglong2 xv01 = *(const ulonglong2*)&xsD[(pl + j) * 16 + rg * 4];
                ulonglong2 xv23 = *(const ulonglong2*)&xsD[(pl + j) * 16 + rg * 4 + 2];
                acc[j][0] = fma2(xv01.x, wv0.x, acc[j][0]);
                acc[j][1] = fma2(xv01.x, wv0.y, acc[j][1]);
                acc[j][0] = fma2(xv01.y, wv1.x, acc[j][0]);
                acc[j][1] = fma2(xv01.y, wv1.y, acc[j][1]);
                acc[j][0] = fma2(xv23.x, wv2.x, acc[j][0]);
                acc[j][1] = fma2(xv23.x, wv2.y, acc[j][1]);
                acc[j][0] = fma2(xv23.y, wv3.x, acc[j][0]);
                acc[j][1] = fma2(xv23.y, wv3.y, acc[j][1]);
            }
        }

        // ---- prefetch own x region for t+1 (warp-private; own reads done above;
        //      LDG latency hides under the h-patch below)
        if (t + 1 < TT) {
            const int base4 = ((((b * TT) + t + 1) * SS + 2 * p0) * CC) >> 2;
            const float4* xsrc = (const float4*)x;
            for (int q = f; q < NP * 4; q += 32) {
                int li = pl * 4 + q;
                int gi = base4 + li;
                float4 v = (gi < XTOT / 4) ? xsrc[gi] : make_float4(0.f, 0.f, 0.f, 0.f);
                xsD[li * 4 + 0] = dup2(v.x);
                xsD[li * 4 + 1] = dup2(v.y);
                xsD[li * 4 + 2] = dup2(v.z);
                xsD[li * 4 + 3] = dup2(v.w);
            }
        }

        // ---- h-patch: row-major merged k0/k1 taps. Row m feeds slot m (k0)
        // and slot m-1 (k1). Last warp's top row is the halo row (SLOTS).
        #pragma unroll
        for (int fg = 0; fg < FF / 2; fg++) {
            ulonglong2 w0a = *(const ulonglong2*)&w4s[(16 + fg * 2 + 0) * FF + f];
            ulonglong2 w0b = *(const ulonglong2*)&w4s[(16 + fg * 2 + 1) * FF + f];
            ulonglong2 w1a = *(const ulonglong2*)&w4s[(16 + FF + fg * 2 + 0) * FF + f];
            ulonglong2 w1b = *(const ulonglong2*)&w4s[(16 + FF + fg * 2 + 1) * FF + f];
            #pragma unroll
            for (int m = 0; m <= NP; m++) {
                ulonglong2 hv = *(const ulonglong2*)&hrd[(pl + m) * FF + fg * 2];
                if (m < NP) {
                    acc[m][0] = fma2(hv.x, w0a.x, acc[m][0]);
                    acc[m][1] = fma2(hv.x, w0a.y, acc[m][1]);
                    acc[m][0] = fma2(hv.y, w0b.x, acc[m][0]);
                    acc[m][1] = fma2(hv.y, w0b.y, acc[m][1]);
                }
                if (m > 0) {
                    acc[m - 1][0] = fma2(hv.x, w1a.x, acc[m - 1][0]);
                    acc[m - 1][1] = fma2(hv.x, w1a.y, acc[m - 1][1]);
                    acc[m - 1][0] = fma2(hv.y, w1b.x, acc[m - 1][0]);
                    acc[m - 1][1] = fma2(hv.y, w1b.y, acc[m - 1][1]);
                }
            }
        }

        // ---- cell update (c in regs), write OTHER parity buffer; halo push.
        // Positions beyond SH (rank 3 tail) masked to h=0 (SAME padding).
        #pragma unroll
        for (int j = 0; j < NP; j++) {
            const int m = pl + j;
            float2 a01 = unpack2(acc[j][0]);   // (zi, zf)
            float2 a23 = unpack2(acc[j][1]);   // (zc, zo)
            float i_g = hsig(a01.x);
            float f_g = hsig(a01.y);
            float cn = f_g * creg[j] + i_g * ftanh(a23.x);
            float hn = hsig(a23.y) * ftanh(cn);
            creg[j] = cn;
            bool ok = (p0 + m) < SH;
            ull hd = dup2(ok ? hn : 0.0f);
            hwr[m * FF + f] = hd;
            if (j == 0 && w == 0 && rank > 0) {
                // left neighbor reads this in its (par^1) buffer halo row
                unsigned la = smem_u32(&hwr[SLOTS * FF + f]);
                unsigned ra;
                asm("mapa.shared::cluster.u32 %0, %1, %2;"
                    : "=r"(ra) : "r"(la), "r"(rank - 1));
                asm volatile("st.shared::cluster.u64 [%0], %1;"
                             :: "r"(ra), "l"(hd) : "memory");
            }
        }

        // single cluster-wide barrier: orders local h writes, warp-private x,
        // and the remote halo push for the next step
        asm volatile("barrier.cluster.arrive.aligned;" ::: "memory");
        asm volatile("barrier.cluster.wait.aligned;" ::: "memory");
    }

    // ---- fused Dense(1): final h is in parity buffer 0 (TT even)
    {
        const ull* hfin = hsD;   // parity 0
        float partial = 0.0f;
        #pragma unroll
        for (int j = 0; j < NP; j++) {
            const int m = pl + j;
            const int p = p0 + m;
            if (p < SH)
                partial += unpack2(hfin[m * FF + f]).x * dw[p * FF + f];
        }
        #pragma unroll
        for (int off = 16; off > 0; off >>= 1)
            partial += __shfl_down_sync(0xffffffffu, partial, off);
        float* red = (float*)xsD;   // reuse x scratch (all compute done)
        if (f == 0) red[w] = partial;
        __syncthreads();
        if (w == 0) {
            float s = (f < NWARPS) ? red[f] : 0.0f;
            #pragma unroll
            for (int off = 16; off > 0; off >>= 1)
                s += __shfl_down_sync(0xffffffffu, s, off);
            if (f == 0) atomicAdd(out + b, s);
        }
    }
}

extern "C" void kernel_launch(void* const* d_in, const int* in_sizes, int n_in,
                              void* d_out, int out_size) {
    const float* x    = (const float*)d_in[0];  // (32,50,2048,8)
    const float* kern = (const float*)d_in[1];  // (2,8,128)
    const float* rk   = (const float*)d_in[2];  // (2,32,128)
    const float* bias = (const float*)d_in[3];  // (128,)
    const float* dw   = (const float*)d_in[4];  // (32768,1)
    const float* db   = (const float*)d_in[5];  // (1,)
    float* out = (float*)d_out;                  // (32,1)

    const int smem_bytes = RDIM * FF * 16 + XS_N * 8 + 2 * HBUF * 8; // 210432
    static int configured = 0;
    if (!configured) {
        cudaFuncSetAttribute(lstm_kernel, cudaFuncAttributeMaxDynamicSharedMemorySize,
                             smem_bytes);
        configured = 1;
    }

    init_out_kernel<<<1, 32>>>(db, out);
    dim3 grid(CLUSTER_X, BB);   // 128 CTAs = 32 clusters of 4 (one batch each)
    lstm_kernel<<<grid, NTHREADS, smem_bytes>>>(x, kern, rk, bias, dw, out);
}

// round 17
// speedup vs baseline: 1.1060x; 1.1060x over previous
#include <cuda_runtime.h>
#include <math.h>

#define BB 32
#define TT 50
#define SS 2048
#define CC 8
#define FF 32
#define SH 1024
#define NG 128          // 4*F gates
#define RDIM 80         // 16 (x patch) + 64 (h patch)
#define POSB 256        // owned output positions per CTA
#define NWARPS 16
#define NP 16           // slots per warp (16*16 = 256, exact)
#define NTHREADS 512
#define HROWS 257       // 256 owned rows + 1 halo row (per parity buffer)
#define HBUF (HROWS*FF) // ull entries per parity buffer
#define XS_N (POSB*16)  // 4096 x entries per step
#define CLUSTER_X 4

typedef unsigned long long ull;

__device__ __forceinline__ float hsig(float x) {
    return __saturatef(fmaf(x, 0.2f, 0.5f));
}

// fast tanh: 1 - 2/(exp(2x)+1); abs err ~1e-6, exact saturation
__device__ __forceinline__ float ftanh(float x) {
    float e = __expf(2.0f * x);
    return 1.0f - __fdividef(2.0f, e + 1.0f);
}

__device__ __forceinline__ ull fma2(ull a, ull b, ull c) {
    ull d;
    asm("fma.rn.f32x2 %0, %1, %2, %3;" : "=l"(d) : "l"(a), "l"(b), "l"(c));
    return d;
}
__device__ __forceinline__ ull dup2(float v) {
    ull d;
    asm("mov.b64 %0, {%1, %1};" : "=l"(d) : "f"(v));
    return d;
}
__device__ __forceinline__ ull pack2(float lo, float hi) {
    ull d;
    asm("mov.b64 %0, {%1, %2};" : "=l"(d) : "f"(lo), "f"(hi));
    return d;
}
__device__ __forceinline__ float2 unpack2(ull d) {
    float lo, hi;
    asm("mov.b64 {%0, %1}, %2;" : "=f"(lo), "=f"(hi) : "l"(d));
    return make_float2(lo, hi);
}
__device__ __forceinline__ unsigned smem_u32(const void* p) {
    unsigned a;
    asm("{ .reg .u64 t; cvta.to.shared.u64 t, %1; cvt.u32.u64 %0, t; }"
        : "=r"(a) : "l"(p));
    return a;
}
__device__ __forceinline__ void cluster_arrive() {
    asm volatile("barrier.cluster.arrive.aligned;" ::: "memory");
}
__device__ __forceinline__ void cluster_wait() {
    asm volatile("barrier.cluster.wait.aligned;" ::: "memory");
}

// out[b] = db[0] before lstm_kernel atomically accumulates the dense dot.
__global__ void init_out_kernel(const float* __restrict__ db, float* __restrict__ out) {
    if (threadIdx.x < BB) out[threadIdx.x] = db[0];
}

// All 50 timesteps + fused Dense(1) in ONE launch.
// Grid (4, 32) = 128 CTAs; cluster (4,1,1) = one batch per cluster.
// Split cluster barrier: arrive after cell update, wait hidden behind the
// next step's x-patch compute + x prefetch.
// smem: w4s 40960B | xsD 32768B | hsD 2*257*32*8 = 131584B -> 205312B
__global__ __launch_bounds__(NTHREADS, 1) __cluster_dims__(CLUSTER_X, 1, 1)
void lstm_kernel(const float* __restrict__ x, const float* __restrict__ kern,
                 const float* __restrict__ rk, const float* __restrict__ bias,
                 const float* __restrict__ dw, float* __restrict__ out) {
    extern __shared__ float smem[];
    float4* w4s = (float4*)smem;                 // 2560 float4
    ull* xsD = (ull*)(smem + RDIM * FF * 4);     // XS_N duplicated pairs
    ull* hsD = xsD + XS_N;                       // 2 parity buffers of HBUF

    const int b = blockIdx.y;
    const int rank = blockIdx.x;                 // cluster cta rank (grid.x == 4)
    const int p0 = rank * POSB;
    const int tid = threadIdx.x;
    const int f = tid & 31;
    const int w = tid >> 5;
    const int pl = w * NP;

    // ---- build weights in smem (once for all 50 steps)
    for (int i = tid; i < RDIM * FF; i += NTHREADS) {
        int r = i >> 5, ff = i & 31;
        const float* src;
        if (r < 16) {
            src = kern + ((r >> 3) * CC + (r & 7)) * NG;
        } else {
            int rr = r - 16;
            src = rk + ((rr >> 5) * FF + (rr & 31)) * NG;
        }
        w4s[i] = make_float4(src[ff], src[32 + ff], src[64 + ff], src[96 + ff]);
    }
    // ---- h state = 0 (both parity buffers incl. halo rows)
    for (int i = tid; i < 2 * HBUF; i += NTHREADS) hsD[i] = 0ULL;
    // ---- x tile for t = 0 (pre-duplicated pairs, warp-private region)
    {
        const float4* xsrc = (const float4*)(x + ((size_t)(b * TT) * SS + 2 * p0) * CC);
        int i0 = pl * 4 + f * 2;   // two float4 per lane, warp-private region
        #pragma unroll
        for (int q = 0; q < 2; q++) {
            float4 v = xsrc[i0 + q];
            xsD[(i0 + q) * 4 + 0] = dup2(v.x);
            xsD[(i0 + q) * 4 + 1] = dup2(v.y);
            xsD[(i0 + q) * 4 + 2] = dup2(v.z);
            xsD[(i0 + q) * 4 + 3] = dup2(v.w);
        }
    }
    // ---- c state in registers for the whole sequence
    float creg[NP];
    #pragma unroll
    for (int j = 0; j < NP; j++) creg[j] = 0.0f;

    const ull b01 = pack2(bias[f], bias[32 + f]);
    const ull b23 = pack2(bias[64 + f], bias[96 + f]);

    // arrive #0: init (incl. remote-targeted halo rows) done
    cluster_arrive();

    for (int t = 0; t < TT; t++) {
        const int par = t & 1;
        ull* hrd = hsD + par * HBUF;          // read current h
        ull* hwr = hsD + (par ^ 1) * HBUF;    // write next h

        ull acc[NP][2];
        #pragma unroll
        for (int j = 0; j < NP; j++) { acc[j][0] = b01; acc[j][1] = b23; }

        // ---- x-patch (r = 0..15): 4-row weight groups, pre-duplicated pairs
        // (uses only warp-private xsD + weights; safe before the cluster wait)
        #pragma unroll
        for (int rg = 0; rg < 4; rg++) {
            ulonglong2 wv0 = *(const ulonglong2*)&w4s[(rg * 4 + 0) * FF + f];
            ulonglong2 wv1 = *(const ulonglong2*)&w4s[(rg * 4 + 1) * FF + f];
            ulonglong2 wv2 = *(const ulonglong2*)&w4s[(rg * 4 + 2) * FF + f];
            ulonglong2 wv3 = *(const ulonglong2*)&w4s[(rg * 4 + 3) * FF + f];
            #pragma unroll
            for (int j = 0; j < NP; j++) {
                ulonglong2 xv01 = *(const ulonglong2*)&xsD[(pl + j) * 16 + rg * 4];
                ulonglong2 xv23 = *(const ulonglong2*)&xsD[(pl + j) * 16 + rg * 4 + 2];
                acc[j][0] = fma2(xv01.x, wv0.x, acc[j][0]);
                acc[j][1] = fma2(xv01.x, wv0.y, acc[j][1]);
                acc[j][0] = fma2(xv01.y, wv1.x, acc[j][0]);
                acc[j][1] = fma2(xv01.y, wv1.y, acc[j][1]);
                acc[j][0] = fma2(xv23.x, wv2.x, acc[j][0]);
                acc[j][1] = fma2(xv23.x, wv2.y, acc[j][1]);
                acc[j][0] = fma2(xv23.y, wv3.x, acc[j][0]);
                acc[j][1] = fma2(xv23.y, wv3.y, acc[j][1]);
            }
        }

        // ---- prefetch own x region for t+1 (warp-private; own reads done above)
        if (t + 1 < TT) {
            const float4* xsrc =
                (const float4*)(x + ((size_t)(b * TT + t + 1) * SS + 2 * p0) * CC);
            int i0 = pl * 4 + f * 2;
            #pragma unroll
            for (int q = 0; q < 2; q++) {
                float4 v = xsrc[i0 + q];
                xsD[(i0 + q) * 4 + 0] = dup2(v.x);
                xsD[(i0 + q) * 4 + 1] = dup2(v.y);
                xsD[(i0 + q) * 4 + 2] = dup2(v.z);
                xsD[(i0 + q) * 4 + 3] = dup2(v.w);
            }
        }

        // wait #t: all CTAs finished step t-1 h writes + halo pushes.
        // Latency hidden behind the x-patch compute above.
        cluster_wait();

        // ---- h-patch: row-major merged k0/k1 taps. Row m feeds slot m (k0)
        // and slot m-1 (k1). Last warp's top row is the halo row (256).
        const int lastrow = (w == NWARPS - 1) ? 256 : (pl + NP);
        #pragma unroll
        for (int fg = 0; fg < FF / 2; fg++) {
            ulonglong2 w0a = *(const ulonglong2*)&w4s[(16 + fg * 2 + 0) * FF + f];
            ulonglong2 w0b = *(const ulonglong2*)&w4s[(16 + fg * 2 + 1) * FF + f];
            ulonglong2 w1a = *(const ulonglong2*)&w4s[(16 + FF + fg * 2 + 0) * FF + f];
            ulonglong2 w1b = *(const ulonglong2*)&w4s[(16 + FF + fg * 2 + 1) * FF + f];
            #pragma unroll
            for (int m = 0; m <= NP; m++) {
                const int row = (m == NP) ? lastrow : (pl + m);
                ulonglong2 hv = *(const ulonglong2*)&hrd[row * FF + fg * 2];
                if (m < NP) {
                    acc[m][0] = fma2(hv.x, w0a.x, acc[m][0]);
                    acc[m][1] = fma2(hv.x, w0a.y, acc[m][1]);
                    acc[m][0] = fma2(hv.y, w0b.x, acc[m][0]);
                    acc[m][1] = fma2(hv.y, w0b.y, acc[m][1]);
                }
                if (m > 0) {
                    acc[m - 1][0] = fma2(hv.x, w1a.x, acc[m - 1][0]);
                    acc[m - 1][1] = fma2(hv.x, w1a.y, acc[m - 1][1]);
                    acc[m - 1][0] = fma2(hv.y, w1b.x, acc[m - 1][0]);
                    acc[m - 1][1] = fma2(hv.y, w1b.y, acc[m - 1][1]);
                }
            }
        }

        // ---- cell update (c in regs), write OTHER parity buffer; halo push
        #pragma unroll
        for (int j = 0; j < NP; j++) {
            float2 a01 = unpack2(acc[j][0]);   // (zi, zf)
            float2 a23 = unpack2(acc[j][1]);   // (zc, zo)
            float i_g = hsig(a01.x);
            float f_g = hsig(a01.y);
            float cn = f_g * creg[j] + i_g * ftanh(a23.x);
            float hn = hsig(a23.y) * ftanh(cn);
            creg[j] = cn;
            ull hd = dup2(hn);
            hwr[(pl + j) * FF + f] = hd;
            if (j == 0 && w == 0 && rank > 0) {
                // left neighbor reads this in its (par^1) buffer halo row
                unsigned la = smem_u32(&hwr[256 * FF + f]);
                unsigned ra;
                asm("mapa.shared::cluster.u32 %0, %1, %2;"
                    : "=r"(ra) : "r"(la), "r"(rank - 1));
                asm volatile("st.shared::cluster.u64 [%0], %1;"
                             :: "r"(ra), "l"(hd) : "memory");
            }
        }

        // arrive #(t+1): this CTA's step-t writes (local h + remote push) done
        cluster_arrive();
    }

    // pair the final arrive before the epilogue / exit
    cluster_wait();

    // ---- fused Dense(1): final h is in parity buffer 0 (TT even).
    // Each thread reads only rows it wrote itself (same lane, same rows).
    {
        const ull* hfin = hsD;   // parity 0
        float partial = 0.0f;
        #pragma unroll
        for (int j = 0; j < NP; j++) {
            const int m = pl + j;
            partial += unpack2(hfin[m * FF + f]).x * dw[(p0 + m) * FF + f];
        }
        #pragma unroll
        for (int off = 16; off > 0; off >>= 1)
            partial += __shfl_down_sync(0xffffffffu, partial, off);
        float* red = (float*)xsD;   // reuse x scratch (all compute done)
        if (f == 0) red[w] = partial;
        __syncthreads();
        if (w == 0) {
            float s = (f < NWARPS) ? red[f] : 0.0f;
            #pragma unroll
            for (int off = 8; off > 0; off >>= 1)
                s += __shfl_down_sync(0xffffffffu, s, off);
            if (f == 0) atomicAdd(out + b, s);
        }
    }
}

extern "C" void kernel_launch(void* const* d_in, const int* in_sizes, int n_in,
                              void* d_out, int out_size) {
    const float* x    = (const float*)d_in[0];  // (32,50,2048,8)
    const float* kern = (const float*)d_in[1];  // (2,8,128)
    const float* rk   = (const float*)d_in[2];  // (2,32,128)
    const float* bias = (const float*)d_in[3];  // (128,)
    const float* dw   = (const float*)d_in[4];  // (32768,1)
    const float* db   = (const float*)d_in[5];  // (1,)
    float* out = (float*)d_out;                  // (32,1)

    const int smem_bytes = RDIM * FF * 16 + XS_N * 8 + 2 * HBUF * 8; // 205312
    static int configured = 0;
    if (!configured) {
        cudaFuncSetAttribute(lstm_kernel, cudaFuncAttributeMaxDynamicSharedMemorySize,
                             smem_bytes);
        configured = 1;
    }

    init_out_kernel<<<1, 32>>>(db, out);
    dim3 grid(CLUSTER_X, BB);   // 128 CTAs = 32 clusters of 4 (one batch each)
    lstm_kernel<<<grid, NTHREADS, smem_bytes>>>(x, kern, rk, bias, dw, out);
}